// round 12
// baseline (speedup 1.0000x reference)
#include <cuda_runtime.h>
#include <cuda_bf16.h>

#define E_MAX   250000
#define A_MAX   10000
#define CHUNK   128

// Scratch (no allocations allowed -> __device__ globals).
__device__ int    g_count[A_MAX];
__device__ int    g_offsets[A_MAX + 1];
__device__ int    g_cursor[A_MAX];
__device__ int    g_atom_order[A_MAX];    // atoms sorted by edge count desc
__device__ int2   g_meta[E_MAX];          // (edge, neighbor) in CSR order
__device__ float4 g_shq[E_MAX * 4];       // 16 sh floats per edge, CSR order

// ---------------------------------------------------------------------------
__global__ void count_kernel(const int* __restrict__ centers, int E) {
    int e = blockIdx.x * blockDim.x + threadIdx.x;
    if (e < E) atomicAdd(&g_count[centers[e]], 1);
}

// Single-block: exclusive scan (offsets + cursors), re-zero g_count, and
// counting-sort atoms by descending edge count (LPT order) into g_atom_order.
__global__ void scan_kernel(int nAtoms, int E) {
    __shared__ int part[1024];
    __shared__ int hist[256];
    __shared__ int hoff[256];
    __shared__ int hscan[256];

    const int tid = threadIdx.x;
    const int chunk = (nAtoms + 1023) >> 10;
    const int b = tid * chunk;
    const int e = min(b + chunk, nAtoms);

    if (tid < 256) hist[tid] = 0;

    int cnt[32];
    int s = 0;
    for (int i = b; i < e; i++) { cnt[i - b] = g_count[i]; s += cnt[i - b]; }
    part[tid] = s;
    __syncthreads();

    for (int i = b; i < e; i++) {
        int c = cnt[i - b]; if (c > 255) c = 255;
        atomicAdd(&hist[c], 1);
    }

    for (int off = 1; off < 1024; off <<= 1) {
        int t = 0;
        if (tid >= off) t = part[tid - off];
        __syncthreads();
        part[tid] += t;
        __syncthreads();
    }

    // Descending bin offsets via reversed inclusive scan.
    if (tid < 256) hscan[tid] = hist[255 - tid];
    __syncthreads();
    for (int off = 1; off < 256; off <<= 1) {
        int t = 0;
        if (tid < 256 && tid >= off) t = hscan[tid - off];
        __syncthreads();
        if (tid < 256) hscan[tid] += t;
        __syncthreads();
    }
    if (tid < 256) hoff[255 - tid] = hscan[tid] - hist[255 - tid];
    __syncthreads();

    int run = part[tid] - s;
    for (int i = b; i < e; i++) {
        g_offsets[i] = run;
        g_cursor[i]  = run;
        run += cnt[i - b];
        g_count[i] = 0;
        int c = cnt[i - b]; if (c > 255) c = 255;
        int pos = atomicAdd(&hoff[c], 1);
        g_atom_order[pos] = i;
    }
    if (tid == 1023) g_offsets[nAtoms] = E;
}

// Scatter + pack: CSR edge list + per-edge sh quads in CSR order so the
// density kernel's staging reads are fully coalesced.
//   q0 = [sh0, sh1_0, sh1_1, sh1_2]
//   q1 = [sh2_0, sh2_1, sh2_2, sh2_3]
//   q2 = [sh2_4, sh3_0, sh3_1, sh3_2]
//   q3 = [sh3_3, sh3_4, sh3_5, sh3_6]
__global__ void scatter_pack_kernel(const int* __restrict__ centers,
                                    const int* __restrict__ neighbors,
                                    const float* __restrict__ sh0,
                                    const float* __restrict__ sh1,
                                    const float* __restrict__ sh2,
                                    const float* __restrict__ sh3,
                                    int E) {
    int e = blockIdx.x * blockDim.x + threadIdx.x;
    if (e >= E) return;
    const int c = centers[e];
    const int p = atomicAdd(&g_cursor[c], 1);
    g_meta[p] = make_int2(e, neighbors[e]);

    const float* s1 = sh1 + (long)e * 3;
    const float* s2 = sh2 + (long)e * 5;
    const float* s3 = sh3 + (long)e * 7;
    float4* dst = g_shq + (long)p * 4;
    dst[0] = make_float4(sh0[e], s1[0], s1[1], s1[2]);
    dst[1] = make_float4(s2[0], s2[1], s2[2], s2[3]);
    dst[2] = make_float4(s2[4], s3[0], s3[1], s3[2]);
    dst[3] = make_float4(s3[3], s3[4], s3[5], s3[6]);
}

// ---------------------------------------------------------------------------
// Per-warp chunk processor. CH channels per lane, MC = 2L+1 m-values.
// acc layout: acc[m*CH + c]. sh comes from SMEM quads (broadcast LDS).
template<int L, int KL, int CH>
__device__ __forceinline__ void chunk_proc(
    float* __restrict__ acc, const int lane,
    const float* __restrict__ rb, const float* __restrict__ emb,
    const int n, const int2* __restrict__ s_meta,
    const float4* __restrict__ s_shq)
{
    constexpr int MC = 2 * L + 1;
    const int k = lane * CH;

    #pragma unroll 2
    for (int i = 0; i < n; i++) {
        const int2 me = s_meta[i];
        const float* rbp = rb  + (long)me.x * KL  + k;
        const float* emp = emb + (long)me.y * 256 + k;

        float p[CH];
        if (CH == 8) {
            float4 a0 = *(const float4*)rbp;
            float4 a1 = *(const float4*)(rbp + 4);
            float4 b0 = *(const float4*)emp;
            float4 b1 = *(const float4*)(emp + 4);
            p[0]=a0.x*b0.x; p[1]=a0.y*b0.y; p[2]=a0.z*b0.z; p[3]=a0.w*b0.w;
            p[4]=a1.x*b1.x; p[5]=a1.y*b1.y; p[6]=a1.z*b1.z; p[7]=a1.w*b1.w;
        } else if (CH == 6) {
            // 24B/lane stride -> only 8B alignment guaranteed: use float2 x3
            float2 a0 = *(const float2*)rbp;
            float2 a1 = *(const float2*)(rbp + 2);
            float2 a2 = *(const float2*)(rbp + 4);
            float2 b0 = *(const float2*)emp;
            float2 b1 = *(const float2*)(emp + 2);
            float2 b2 = *(const float2*)(emp + 4);
            p[0]=a0.x*b0.x; p[1]=a0.y*b0.y; p[2]=a1.x*b1.x;
            p[3]=a1.y*b1.y; p[4]=a2.x*b2.x; p[5]=a2.y*b2.y;
        } else if (CH == 4) {
            float4 a = *(const float4*)rbp;
            float4 b = *(const float4*)emp;
            p[0]=a.x*b.x; p[1]=a.y*b.y; p[2]=a.z*b.z; p[3]=a.w*b.w;
        } else {
            float2 a = *(const float2*)rbp;
            float2 b = *(const float2*)emp;
            p[0]=a.x*b.x; p[1]=a.y*b.y;
        }

        float sh[MC];
        if (L == 0) {
            sh[0] = ((const float*)s_shq)[i * 16];
        } else if (L == 1) {
            const float4 q0 = s_shq[i * 4];
            sh[0] = q0.y; sh[1] = q0.z; sh[2] = q0.w;
        } else if (L == 2) {
            const float4 q1 = s_shq[i * 4 + 1];
            const float4 q2 = s_shq[i * 4 + 2];
            sh[0]=q1.x; sh[1]=q1.y; sh[2]=q1.z; sh[3]=q1.w; sh[4]=q2.x;
        } else {
            const float4 q2 = s_shq[i * 4 + 2];
            const float4 q3 = s_shq[i * 4 + 3];
            sh[0]=q2.y; sh[1]=q2.z; sh[2]=q2.w;
            sh[3]=q3.x; sh[4]=q3.y; sh[5]=q3.z; sh[6]=q3.w;
        }

        #pragma unroll
        for (int m = 0; m < MC; m++)
            #pragma unroll
            for (int c = 0; c < CH; c++)
                acc[m * CH + c] += sh[m] * p[c];
    }
}

// One CTA per atom (LPT order), 128 threads = 4 fully-active warps:
//   w0: l0, 8 ch/lane   w1: l1, 6 ch/lane
//   w2: l2, 4 ch/lane   w3: l3, 2 ch/lane
__global__ void __launch_bounds__(128, 10)
density_kernel(const float* __restrict__ rb0, const float* __restrict__ rb1,
               const float* __restrict__ rb2, const float* __restrict__ rb3,
               const float* __restrict__ emb,
               float* __restrict__ out, int nAtoms)
{
    const int atom = g_atom_order[blockIdx.x];
    const int tid  = threadIdx.x;
    const int wid  = tid >> 5;
    const int lane = tid & 31;

    __shared__ int2   s_meta[CHUNK];
    __shared__ float4 s_shq[CHUNK * 4];

    const long B1 = (long)nAtoms * 256;
    const long B2 = B1 + (long)nAtoms * 576;
    const long B3 = B2 + (long)nAtoms * 640;

    const int start = g_offsets[atom];
    const int cnt   = g_offsets[atom + 1] - start;

    float acc[20];
    #pragma unroll
    for (int i = 0; i < 20; i++) acc[i] = 0.f;

    for (int base = 0; base < cnt; base += CHUNK) {
        const int n = min(CHUNK, cnt - base);
        // Stage meta + sh quads (coalesced: CSR-contiguous).
        for (int i = tid; i < n; i += 128)
            s_meta[i] = g_meta[start + base + i];
        for (int idx = tid; idx < n * 4; idx += 128)
            s_shq[idx] = g_shq[(long)(start + base) * 4 + idx];
        __syncthreads();

        if (wid == 0)      chunk_proc<0, 256, 8>(acc, lane, rb0, emb, n, s_meta, s_shq);
        else if (wid == 1) chunk_proc<1, 192, 6>(acc, lane, rb1, emb, n, s_meta, s_shq);
        else if (wid == 2) chunk_proc<2, 128, 4>(acc, lane, rb2, emb, n, s_meta, s_shq);
        else               chunk_proc<3,  64, 2>(acc, lane, rb3, emb, n, s_meta, s_shq);
        __syncthreads();
    }

    // Stores (each element written exactly once).
    if (wid == 0) {
        float* o = out + (long)atom * 256 + lane * 8;
        *(float4*)o       = make_float4(acc[0], acc[1], acc[2], acc[3]);
        *(float4*)(o + 4) = make_float4(acc[4], acc[5], acc[6], acc[7]);
    } else if (wid == 1) {
        float* o = out + B1 + (long)atom * 576 + lane * 6;
        #pragma unroll
        for (int m = 0; m < 3; m++) {
            float* om = o + (long)m * 192;
            *(float2*)om       = make_float2(acc[m*6+0], acc[m*6+1]);
            *(float2*)(om + 2) = make_float2(acc[m*6+2], acc[m*6+3]);
            *(float2*)(om + 4) = make_float2(acc[m*6+4], acc[m*6+5]);
        }
    } else if (wid == 2) {
        float* o = out + B2 + (long)atom * 640 + lane * 4;
        #pragma unroll
        for (int m = 0; m < 5; m++)
            *(float4*)(o + (long)m * 128) =
                make_float4(acc[m*4+0], acc[m*4+1], acc[m*4+2], acc[m*4+3]);
    } else {
        float* o = out + B3 + (long)atom * 448 + lane * 2;
        #pragma unroll
        for (int m = 0; m < 7; m++)
            *(float2*)(o + (long)m * 64) = make_float2(acc[m*2+0], acc[m*2+1]);
    }
}

// ---------------------------------------------------------------------------
extern "C" void kernel_launch(void* const* d_in, const int* in_sizes, int n_in,
                              void* d_out, int out_size)
{
    const float* sh[4];
    const float* rb[4];
    const bool interleaved = ((long)in_sizes[1] > (long)in_sizes[0] * 8);
    for (int l = 0; l < 4; l++) {
        if (interleaved) {
            sh[l] = (const float*)d_in[2 * l];
            rb[l] = (const float*)d_in[2 * l + 1];
        } else {
            sh[l] = (const float*)d_in[l];
            rb[l] = (const float*)d_in[4 + l];
        }
    }
    const float* emb       = (const float*)d_in[8];
    const int*   centers   = (const int*)d_in[9];
    const int*   neighbors = (const int*)d_in[10];
    float*       out       = (float*)d_out;

    const int E      = in_sizes[9];
    const int nAtoms = in_sizes[8] / 256;

    const int TB = 256;
    count_kernel       <<<(E + TB - 1) / TB, TB>>>(centers, E);
    scan_kernel        <<<1, 1024>>>(nAtoms, E);
    scatter_pack_kernel<<<(E + TB - 1) / TB, TB>>>(centers, neighbors,
                                                   sh[0], sh[1], sh[2], sh[3], E);
    density_kernel     <<<nAtoms, 128>>>(rb[0], rb[1], rb[2], rb[3],
                                         emb, out, nAtoms);
}